// round 1
// baseline (speedup 1.0000x reference)
#include <cuda_runtime.h>
#include <math.h>

#define NQ 4096
#define NK 32768
#define DIN 1024
#define DQK 512
#define DV 512

// ---------------- scratch (no allocations allowed) ----------------
__device__ float g_Q[(size_t)NQ * DQK];
__device__ float g_K[(size_t)NK * DQK];
__device__ float g_V[(size_t)NK * DV];
__device__ float g_P[NK];      // scores, then exp(p)
__device__ int   g_Mord[NQ];   // per-query max (ordered-int float)
__device__ float g_Den[NQ];    // per-query softmax denominator

// ---------------- packed f32x2 helpers (sm_103a) ----------------
__device__ __forceinline__ void fma2(unsigned long long& d,
                                     unsigned long long a,
                                     unsigned long long b) {
    asm("fma.rn.f32x2 %0, %1, %2, %0;" : "+l"(d) : "l"(a), "l"(b));
}
__device__ __forceinline__ unsigned long long splat2(float x) {
    unsigned long long r;
    asm("mov.b64 %0, {%1, %1};" : "=l"(r) : "f"(x));
    return r;
}
__device__ __forceinline__ void unpack2(unsigned long long v, float& x, float& y) {
    asm("mov.b64 {%0, %1}, %2;" : "=f"(x), "=f"(y) : "l"(v));
}

// ---------------- ordered-int float max helpers ----------------
__device__ __forceinline__ int f2ord(float f) {
    int i = __float_as_int(f);
    return (i >= 0) ? i : (i ^ 0x7FFFFFFF);
}
__device__ __forceinline__ float ord2f(int i) {
    return __int_as_float(i >= 0 ? i : (i ^ 0x7FFFFFFF));
}

// ---------------- SGEMM with bias: C[M,512] = A[M,1024] @ B[1024,512] + bias ----------------
#define BM 128
#define BN 128
#define BK 8

__global__ __launch_bounds__(256, 2)
void sgemm_bias_kernel(const float* __restrict__ A, const float* __restrict__ B,
                       const float* __restrict__ bias, float* __restrict__ C,
                       int M, int N, int K)
{
    __shared__ float As[2][BK][BM];
    __shared__ float Bs[2][BK][BN];

    const int tid   = threadIdx.x;
    const int tr    = (tid >> 4) << 3;   // micro-tile row base (0..120, multiple of 8)
    const int tc    = (tid & 15) << 3;   // micro-tile col base
    const int a_row = tid >> 1;          // 0..127
    const int a_col = (tid & 1) << 2;    // 0 or 4
    const int b_row = tid >> 5;          // 0..7
    const int b_col = (tid & 31) << 2;   // 0..124

    const float* Ag = A + (size_t)(blockIdx.y * BM) * K;
    const float* Bg = B + blockIdx.x * BN;

    unsigned long long acc[32];          // 4 M-pairs x 8 N, packed along M
    #pragma unroll
    for (int i = 0; i < 32; i++) acc[i] = 0ull;

    float4 av = *(const float4*)(Ag + (size_t)a_row * K + a_col);
    float4 bv = *(const float4*)(Bg + (size_t)b_row * N + b_col);
    As[0][a_col + 0][a_row] = av.x;
    As[0][a_col + 1][a_row] = av.y;
    As[0][a_col + 2][a_row] = av.z;
    As[0][a_col + 3][a_row] = av.w;
    *(float4*)&Bs[0][b_row][b_col] = bv;
    __syncthreads();

    const int nIter = K / BK;
    for (int it = 0; it < nIter; it++) {
        const int cur = it & 1;
        if (it + 1 < nIter) {
            av = *(const float4*)(Ag + (size_t)a_row * K + (it + 1) * BK + a_col);
            bv = *(const float4*)(Bg + (size_t)((it + 1) * BK + b_row) * N + b_col);
        }
        #pragma unroll
        for (int k = 0; k < BK; k++) {
            unsigned long long a2[4];
            const unsigned long long* ap =
                (const unsigned long long*)&As[cur][k][tr];   // 8B-aligned (tr even)
            a2[0] = ap[0]; a2[1] = ap[1]; a2[2] = ap[2]; a2[3] = ap[3];
            unsigned long long b2[8];
            #pragma unroll
            for (int j = 0; j < 8; j++) b2[j] = splat2(Bs[cur][k][tc + j]);
            #pragma unroll
            for (int i2 = 0; i2 < 4; i2++) {
                #pragma unroll
                for (int j = 0; j < 8; j++)
                    fma2(acc[i2 * 8 + j], a2[i2], b2[j]);
            }
        }
        if (it + 1 < nIter) {
            const int nxt = cur ^ 1;
            As[nxt][a_col + 0][a_row] = av.x;
            As[nxt][a_col + 1][a_row] = av.y;
            As[nxt][a_col + 2][a_row] = av.z;
            As[nxt][a_col + 3][a_row] = av.w;
            *(float4*)&Bs[nxt][b_row][b_col] = bv;
        }
        __syncthreads();
    }

    // epilogue: unpack, add bias, vectorized store
    float accf[8][8];
    #pragma unroll
    for (int i2 = 0; i2 < 4; i2++) {
        #pragma unroll
        for (int j = 0; j < 8; j++)
            unpack2(acc[i2 * 8 + j], accf[2 * i2][j], accf[2 * i2 + 1][j]);
    }
    const int colbase = blockIdx.x * BN + tc;
    float bias8[8];
    #pragma unroll
    for (int j = 0; j < 8; j++) bias8[j] = bias[colbase + j];
    const int rowbase = blockIdx.y * BM + tr;
    #pragma unroll
    for (int r = 0; r < 8; r++) {
        float* crow = C + (size_t)(rowbase + r) * N + colbase;
        float4 o0 = make_float4(accf[r][0] + bias8[0], accf[r][1] + bias8[1],
                                accf[r][2] + bias8[2], accf[r][3] + bias8[3]);
        float4 o1 = make_float4(accf[r][4] + bias8[4], accf[r][5] + bias8[5],
                                accf[r][6] + bias8[6], accf[r][7] + bias8[7]);
        *(float4*)(crow)     = o0;
        *(float4*)(crow + 4) = o1;
    }
}

// ---------------- init: zero output, reset max/denominator ----------------
__global__ void init_kernel(float* __restrict__ out) {
    int i = blockIdx.x * blockDim.x + threadIdx.x;
    if (i < NQ * DV) out[i] = 0.0f;
    if (i < NQ) {
        g_Mord[i] = 0x80000000;  // below any ordered float
        g_Den[i]  = 0.0f;
    }
}

// ---------------- scores: warp per key, s_j = Q[row_map[j]] . K[j] * scale ----------------
__global__ void score_kernel(const int* __restrict__ row_map) {
    const int j    = blockIdx.x * 8 + (threadIdx.x >> 5);
    const int lane = threadIdx.x & 31;
    const int qi   = row_map[j];
    const float4* q4 = (const float4*)(g_Q + (size_t)qi * DQK);
    const float4* k4 = (const float4*)(g_K + (size_t)j * DQK);
    float s = 0.0f;
    #pragma unroll
    for (int t = 0; t < 4; t++) {
        float4 a = q4[lane + 32 * t];
        float4 b = k4[lane + 32 * t];
        s += a.x * b.x + a.y * b.y + a.z * b.z + a.w * b.w;
    }
    #pragma unroll
    for (int off = 16; off > 0; off >>= 1)
        s += __shfl_down_sync(0xFFFFFFFFu, s, off);
    if (lane == 0) {
        s *= 0.044194173824159216f;  // 1/sqrt(512)
        g_P[j] = s;
        atomicMax(&g_Mord[qi], f2ord(s));
    }
}

// ---------------- exp + segment denominator ----------------
__global__ void exp_kernel(const int* __restrict__ row_map) {
    const int j = blockIdx.x * blockDim.x + threadIdx.x;
    if (j >= NK) return;
    const int qi = row_map[j];
    const float m = ord2f(g_Mord[qi]);
    const float p = expf(g_P[j] - m);
    g_P[j] = p;
    atomicAdd(&g_Den[qi], p);
}

// ---------------- weighted scatter: out[qi] += (p_j/den_qi) * V[j] ----------------
__global__ void scatter_kernel(const int* __restrict__ row_map, float* __restrict__ out) {
    const int j    = blockIdx.x * 8 + (threadIdx.x >> 5);
    const int lane = threadIdx.x & 31;
    const int qi   = row_map[j];
    const float w  = g_P[j] / g_Den[qi];
    const float4* v4 = (const float4*)(g_V + (size_t)j * DV);
    float* o = out + (size_t)qi * DV;
    #pragma unroll
    for (int t = 0; t < 4; t++) {
        const int e = lane + 32 * t;
        float4 v = v4[e];
        const int d = e * 4;
        atomicAdd(o + d + 0, w * v.x);
        atomicAdd(o + d + 1, w * v.y);
        atomicAdd(o + d + 2, w * v.z);
        atomicAdd(o + d + 3, w * v.w);
    }
}

// ---------------- launcher ----------------
extern "C" void kernel_launch(void* const* d_in, const int* in_sizes, int n_in,
                              void* d_out, int out_size)
{
    const float* X1 = (const float*)d_in[0];
    const float* X2 = (const float*)d_in[1];
    const float* Wq = (const float*)d_in[2];
    const float* bq = (const float*)d_in[3];
    const float* Wk = (const float*)d_in[4];
    const float* bk = (const float*)d_in[5];
    const float* Wv = (const float*)d_in[6];
    const float* bv = (const float*)d_in[7];
    const int*   row_map = (const int*)d_in[8];
    float* out = (float*)d_out;

    float *Qp, *Kp, *Vp;
    cudaGetSymbolAddress((void**)&Qp, g_Q);
    cudaGetSymbolAddress((void**)&Kp, g_K);
    cudaGetSymbolAddress((void**)&Vp, g_V);

    sgemm_bias_kernel<<<dim3(DQK / BN, NQ / BM), 256>>>(X1, Wq, bq, Qp, NQ, DQK, DIN);
    sgemm_bias_kernel<<<dim3(DQK / BN, NK / BM), 256>>>(X2, Wk, bk, Kp, NK, DQK, DIN);
    sgemm_bias_kernel<<<dim3(DV  / BN, NK / BM), 256>>>(X2, Wv, bv, Vp, NK, DV,  DIN);

    init_kernel<<<(NQ * DV + 255) / 256, 256>>>(out);
    score_kernel<<<NK / 8, 256>>>(row_map);
    exp_kernel<<<NK / 256, 256>>>(row_map);
    scatter_kernel<<<NK / 8, 256>>>(row_map, out);
}

// round 3
// speedup vs baseline: 2.0511x; 2.0511x over previous
#include <cuda_runtime.h>
#include <cuda_bf16.h>
#include <math.h>
#include <stdint.h>

#define NQ 4096
#define NK 32768
#define DIN 1024
#define DQK 512
#define DV 512

// ---------------- scratch (no allocations allowed) ----------------
__device__ __nv_bfloat16 g_X1h[(size_t)NQ * DIN];
__device__ __nv_bfloat16 g_X1l[(size_t)NQ * DIN];
__device__ __nv_bfloat16 g_X2h[(size_t)NK * DIN];
__device__ __nv_bfloat16 g_X2l[(size_t)NK * DIN];
__device__ __nv_bfloat16 g_Wth[3 * 512 * DIN];   // transposed weights [n][k], hi
__device__ __nv_bfloat16 g_Wtl[3 * 512 * DIN];   // transposed weights [n][k], lo
__device__ float g_Q[(size_t)NQ * DQK];
__device__ float g_K[(size_t)NK * DQK];
__device__ float g_V[(size_t)NK * DV];
__device__ float g_S[NK];                 // per-key score
__device__ int   g_cnt[NQ];
__device__ int   g_off[NQ + 1];
__device__ int   g_cur[NQ];
__device__ int   g_idx[NK];

// ---------------- PTX helpers (all portable sm_80+) ----------------
__device__ __forceinline__ void cp16(uint32_t dst, const void* src) {
    asm volatile("cp.async.cg.shared.global [%0], [%1], 16;" :: "r"(dst), "l"(src));
}
__device__ __forceinline__ void cp_commit() {
    asm volatile("cp.async.commit_group;" ::: "memory");
}
template <int N> __device__ __forceinline__ void cp_wait() {
    asm volatile("cp.async.wait_group %0;" :: "n"(N) : "memory");
}
__device__ __forceinline__ void ldsm4(uint32_t* r, uint32_t addr) {
    asm volatile("ldmatrix.sync.aligned.m8n8.x4.shared.b16 {%0,%1,%2,%3}, [%4];"
                 : "=r"(r[0]), "=r"(r[1]), "=r"(r[2]), "=r"(r[3]) : "r"(addr));
}
__device__ __forceinline__ void mma16816(float* c, const uint32_t* a, const uint32_t* b) {
    asm volatile(
        "mma.sync.aligned.m16n8k16.row.col.f32.bf16.bf16.f32 "
        "{%0,%1,%2,%3}, {%4,%5,%6,%7}, {%8,%9}, {%0,%1,%2,%3};"
        : "+f"(c[0]), "+f"(c[1]), "+f"(c[2]), "+f"(c[3])
        : "r"(a[0]), "r"(a[1]), "r"(a[2]), "r"(a[3]), "r"(b[0]), "r"(b[1]));
}

// ---------------- smem layout for bf16 GEMM ----------------
// Per stage: A tile 128 rows x 32 bf16 (padded to 40 b16 = 80B rows) = 10240B,
//            B tile 128 rows x 32 bf16 (same padding)                = 10240B.
#define ROWB 80                     // padded row stride in bytes
#define TILE_BYTES 10240
#define STAGE_BYTES 20480
#define NSTAGE 4
#define GEMM_SMEM (NSTAGE * STAGE_BYTES)   // 81920

// ---------------- bf16 HMMA GEMM: C[M,512] = Ah*Bh + Ah*Bl + Al*Bh + bias ----------------
// A: [M,1024] bf16 row-major (hi/lo). B: [512,1024] bf16 ([n][k], pre-transposed hi/lo).
// grid = (512/128, M/128), block = 256 (8 warps, 2x4), warp tile 64x32.
__global__ __launch_bounds__(256, 2)
void gemm3_kernel(const __nv_bfloat16* __restrict__ Ah, const __nv_bfloat16* __restrict__ Al,
                  const __nv_bfloat16* __restrict__ Bh, const __nv_bfloat16* __restrict__ Bl,
                  const float* __restrict__ bias, float* __restrict__ C)
{
    extern __shared__ char smem[];
    const uint32_t sb = (uint32_t)__cvta_generic_to_shared(smem);
    const int tid = threadIdx.x, wid = tid >> 5, lane = tid & 31;
    const int warp_m = wid & 1, warp_n = wid >> 1;
    const int m_base = blockIdx.y * 128;
    const int n_base = blockIdx.x * 128;

    const __nv_bfloat16* pA[3] = {Ah, Ah, Al};
    const __nv_bfloat16* pB[3] = {Bh, Bl, Bh};

    float acc[4][4][4];
    #pragma unroll
    for (int i = 0; i < 4; i++)
        #pragma unroll
        for (int j = 0; j < 4; j++)
            #pragma unroll
            for (int k = 0; k < 4; k++) acc[i][j][k] = 0.0f;

    // per-thread load slots: 4 x 16B per stage (2 for A, 2 for B)
    const int ar0 = tid >> 2, ac0 = tid & 3;        // A rows 0..63
    const int ar1 = ar0 + 64;                        // A rows 64..127
    auto issue_loads = [&](int gi) {
        const int t = gi >> 5, koff = (gi & 31) * 32, s = gi & 3;
        const uint32_t sa  = sb + s * STAGE_BYTES;
        const uint32_t sbm = sa + TILE_BYTES;
        const __nv_bfloat16* A = pA[t];
        const __nv_bfloat16* B = pB[t];
        cp16(sa + ar0 * ROWB + ac0 * 16, A + (size_t)(m_base + ar0) * DIN + koff + ac0 * 8);
        cp16(sa + ar1 * ROWB + ac0 * 16, A + (size_t)(m_base + ar1) * DIN + koff + ac0 * 8);
        cp16(sbm + ar0 * ROWB + ac0 * 16, B + (size_t)(n_base + ar0) * DIN + koff + ac0 * 8);
        cp16(sbm + ar1 * ROWB + ac0 * 16, B + (size_t)(n_base + ar1) * DIN + koff + ac0 * 8);
        cp_commit();
    };

    issue_loads(0);
    issue_loads(1);
    issue_loads(2);

    // ldmatrix address components (constant per thread)
    const int a_row_in = warp_m * 64 + (lane & 15);       // + mf*16
    const int a_colb   = (lane >> 4) * 16;                 // + kh*32 (bytes)
    const int b_row_in = warp_n * 32 + ((lane >> 4) << 3) + (lane & 7);   // + nf2*16
    const int b_colb   = ((lane >> 3) & 1) * 16;           // + kh*32 (bytes)

    const int NSTEP = 96;                                  // 3 terms x 32 K-chunks
    for (int gi = 0; gi < NSTEP; gi++) {
        cp_wait<2>();
        __syncthreads();
        if (gi + 3 < NSTEP) issue_loads(gi + 3); else cp_commit();

        const int s = gi & 3;
        const uint32_t sa  = sb + s * STAGE_BYTES;
        const uint32_t sbm = sa + TILE_BYTES;
        #pragma unroll
        for (int kh = 0; kh < 2; kh++) {
            uint32_t af[4][4], bf[2][4];
            #pragma unroll
            for (int mf = 0; mf < 4; mf++)
                ldsm4(af[mf], sa + (a_row_in + mf * 16) * ROWB + kh * 32 + a_colb);
            #pragma unroll
            for (int nf2 = 0; nf2 < 2; nf2++)
                ldsm4(bf[nf2], sbm + (b_row_in + nf2 * 16) * ROWB + kh * 32 + b_colb);
            #pragma unroll
            for (int mf = 0; mf < 4; mf++) {
                #pragma unroll
                for (int nf = 0; nf < 4; nf++)
                    mma16816(acc[mf][nf], af[mf], &bf[nf >> 1][(nf & 1) * 2]);
            }
        }
    }
    cp_wait<0>();

    // epilogue: add bias, store fp32
    const int col0 = n_base + warp_n * 32 + (lane & 3) * 2;
    const int r0   = m_base + warp_m * 64 + (lane >> 2);
    #pragma unroll
    for (int mf = 0; mf < 4; mf++) {
        #pragma unroll
        for (int nf = 0; nf < 4; nf++) {
            const int col = col0 + nf * 8;
            const float b0 = bias[col], b1 = bias[col + 1];
            float* p0 = C + (size_t)(r0 + mf * 16) * 512 + col;
            float* p1 = p0 + 8 * 512;
            *(float2*)p0 = make_float2(acc[mf][nf][0] + b0, acc[mf][nf][1] + b1);
            *(float2*)p1 = make_float2(acc[mf][nf][2] + b0, acc[mf][nf][3] + b1);
        }
    }
}

// ---------------- fp32 -> bf16 hi/lo split ----------------
__global__ void split_kernel(const float* __restrict__ x,
                             __nv_bfloat16* __restrict__ h, __nv_bfloat16* __restrict__ l)
{
    const size_t i = 4 * ((size_t)blockIdx.x * 256 + threadIdx.x);
    float4 v = *(const float4*)(x + i);
    __nv_bfloat16 h0 = __float2bfloat16(v.x), h1 = __float2bfloat16(v.y);
    __nv_bfloat16 h2 = __float2bfloat16(v.z), h3 = __float2bfloat16(v.w);
    __nv_bfloat16 l0 = __float2bfloat16(v.x - __bfloat162float(h0));
    __nv_bfloat16 l1 = __float2bfloat16(v.y - __bfloat162float(h1));
    __nv_bfloat16 l2 = __float2bfloat16(v.z - __bfloat162float(h2));
    __nv_bfloat16 l3 = __float2bfloat16(v.w - __bfloat162float(h3));
    __nv_bfloat162 hp0 = {h0, h1}, hp1 = {h2, h3}, lp0 = {l0, l1}, lp1 = {l2, l3};
    *(__nv_bfloat162*)(h + i)     = hp0;
    *(__nv_bfloat162*)(h + i + 2) = hp1;
    *(__nv_bfloat162*)(l + i)     = lp0;
    *(__nv_bfloat162*)(l + i + 2) = lp1;
}

// ---------------- W[k][n] (1024x512) -> Wt[n][k] hi/lo split ----------------
__global__ void wtrans_kernel(const float* __restrict__ W,
                              __nv_bfloat16* __restrict__ Th, __nv_bfloat16* __restrict__ Tl)
{
    __shared__ float tile[32][33];
    const int n0 = blockIdx.x * 32, k0 = blockIdx.y * 32;
    const int tx = threadIdx.x, ty = threadIdx.y;
    tile[ty][tx] = W[(size_t)(k0 + ty) * 512 + (n0 + tx)];
    __syncthreads();
    const float v = tile[tx][ty];                  // W[k0+tx][n0+ty]
    const __nv_bfloat16 h = __float2bfloat16(v);
    const __nv_bfloat16 l = __float2bfloat16(v - __bfloat162float(h));
    const size_t o = (size_t)(n0 + ty) * DIN + (k0 + tx);
    Th[o] = h;
    Tl[o] = l;
}

// ---------------- CSR build ----------------
__global__ void zero_cnt_kernel() {
    const int i = blockIdx.x * 256 + threadIdx.x;
    if (i < NQ) g_cnt[i] = 0;
}
__global__ void hist_kernel(const int* __restrict__ row_map) {
    const int j = blockIdx.x * 256 + threadIdx.x;
    if (j < NK) atomicAdd(&g_cnt[row_map[j]], 1);
}
__global__ void scan_kernel() {
    __shared__ int ssum[1024];
    const int t = threadIdx.x;
    const int4 c = *(const int4*)&g_cnt[4 * t];
    const int s = c.x + c.y + c.z + c.w;
    ssum[t] = s;
    __syncthreads();
    int run = s;
    for (int d = 1; d < 1024; d <<= 1) {
        int v = (t >= d) ? ssum[t - d] : 0;
        __syncthreads();
        ssum[t] += v;
        __syncthreads();
    }
    const int excl = ssum[t] - run;
    g_off[4 * t + 0] = excl;
    g_off[4 * t + 1] = excl + c.x;
    g_off[4 * t + 2] = excl + c.x + c.y;
    g_off[4 * t + 3] = excl + c.x + c.y + c.z;
    g_cur[4 * t + 0] = excl;
    g_cur[4 * t + 1] = excl + c.x;
    g_cur[4 * t + 2] = excl + c.x + c.y;
    g_cur[4 * t + 3] = excl + c.x + c.y + c.z;
    if (t == 1023) g_off[NQ] = ssum[t];
}
__global__ void fill_kernel(const int* __restrict__ row_map) {
    const int j = blockIdx.x * 256 + threadIdx.x;
    if (j < NK) {
        const int pos = atomicAdd(&g_cur[row_map[j]], 1);
        g_idx[pos] = j;
    }
}

// ---------------- scores: warp per key, s_j = Q[row_map[j]] . K[j] * scale ----------------
__global__ void score_kernel(const int* __restrict__ row_map) {
    const int j    = blockIdx.x * 8 + (threadIdx.x >> 5);
    const int lane = threadIdx.x & 31;
    const int qi   = row_map[j];
    const float4* q4 = (const float4*)(g_Q + (size_t)qi * DQK);
    const float4* k4 = (const float4*)(g_K + (size_t)j * DQK);
    float s = 0.0f;
    #pragma unroll
    for (int t = 0; t < 4; t++) {
        float4 a = q4[lane + 32 * t];
        float4 b = k4[lane + 32 * t];
        s += a.x * b.x + a.y * b.y + a.z * b.z + a.w * b.w;
    }
    #pragma unroll
    for (int off = 16; off > 0; off >>= 1)
        s += __shfl_down_sync(0xFFFFFFFFu, s, off);
    if (lane == 0) g_S[j] = s * 0.044194173824159216f;   // 1/sqrt(512)
}

// ---------------- gather: per-query softmax + weighted V sum ----------------
__global__ void gather_kernel(float* __restrict__ out) {
    const int qi = blockIdx.x;
    const int s = g_off[qi], e = g_off[qi + 1];
    const int c = threadIdx.x;                    // owns cols 4c..4c+3
    float* o = out + (size_t)qi * DV + c * 4;
    if (e == s) {
        *(float4*)o = make_float4(0.f, 0.f, 0.f, 0.f);
        return;
    }
    float m = -1e30f;
    for (int t = s; t < e; t++) m = fmaxf(m, g_S[g_idx[t]]);
    float4 acc = make_float4(0.f, 0.f, 0.f, 0.f);
    float den = 0.0f;
    for (int t = s; t < e; t++) {
        const int j = g_idx[t];
        const float w = expf(g_S[j] - m);
        den += w;
        const float4 v = *(const float4*)(g_V + (size_t)j * DV + c * 4);
        acc.x += w * v.x; acc.y += w * v.y; acc.z += w * v.z; acc.w += w * v.w;
    }
    const float inv = 1.0f / den;
    *(float4*)o = make_float4(acc.x * inv, acc.y * inv, acc.z * inv, acc.w * inv);
}

// ---------------- launcher ----------------
extern "C" void kernel_launch(void* const* d_in, const int* in_sizes, int n_in,
                              void* d_out, int out_size)
{
    const float* X1 = (const float*)d_in[0];
    const float* X2 = (const float*)d_in[1];
    const float* Wq = (const float*)d_in[2];
    const float* bq = (const float*)d_in[3];
    const float* Wk = (const float*)d_in[4];
    const float* bk = (const float*)d_in[5];
    const float* Wv = (const float*)d_in[6];
    const float* bv = (const float*)d_in[7];
    const int*   row_map = (const int*)d_in[8];
    float* out = (float*)d_out;

    __nv_bfloat16 *x1h, *x1l, *x2h, *x2l, *wth, *wtl;
    float *Qp, *Kp, *Vp;
    cudaGetSymbolAddress((void**)&x1h, g_X1h);
    cudaGetSymbolAddress((void**)&x1l, g_X1l);
    cudaGetSymbolAddress((void**)&x2h, g_X2h);
    cudaGetSymbolAddress((void**)&x2l, g_X2l);
    cudaGetSymbolAddress((void**)&wth, g_Wth);
    cudaGetSymbolAddress((void**)&wtl, g_Wtl);
    cudaGetSymbolAddress((void**)&Qp, g_Q);
    cudaGetSymbolAddress((void**)&Kp, g_K);
    cudaGetSymbolAddress((void**)&Vp, g_V);

    cudaFuncSetAttribute(gemm3_kernel, cudaFuncAttributeMaxDynamicSharedMemorySize, GEMM_SMEM);

    // splits + weight transpose
    split_kernel<<<(NQ * DIN) / 1024, 256>>>(X1, x1h, x1l);
    split_kernel<<<(NK * DIN) / 1024, 256>>>(X2, x2h, x2l);
    wtrans_kernel<<<dim3(512 / 32, DIN / 32), dim3(32, 32)>>>(Wq, wth + 0 * 512 * DIN, wtl + 0 * 512 * DIN);
    wtrans_kernel<<<dim3(512 / 32, DIN / 32), dim3(32, 32)>>>(Wk, wth + 1 * 512 * DIN, wtl + 1 * 512 * DIN);
    wtrans_kernel<<<dim3(512 / 32, DIN / 32), dim3(32, 32)>>>(Wv, wth + 2 * 512 * DIN, wtl + 2 * 512 * DIN);

    // HMMA projections
    gemm3_kernel<<<dim3(4, NQ / 128), 256, GEMM_SMEM>>>(x1h, x1l, wth + 0 * 512 * DIN, wtl + 0 * 512 * DIN, bq, Qp);
    gemm3_kernel<<<dim3(4, NK / 128), 256, GEMM_SMEM>>>(x2h, x2l, wth + 1 * 512 * DIN, wtl + 1 * 512 * DIN, bk, Kp);
    gemm3_kernel<<<dim3(4, NK / 128), 256, GEMM_SMEM>>>(x2h, x2l, wth + 2 * 512 * DIN, wtl + 2 * 512 * DIN, bv, Vp);

    // CSR over row_map
    zero_cnt_kernel<<<NQ / 256, 256>>>();
    hist_kernel<<<NK / 256, 256>>>(row_map);
    scan_kernel<<<1, 1024>>>();
    fill_kernel<<<NK / 256, 256>>>(row_map);

    // degenerate attention
    score_kernel<<<NK / 8, 256>>>(row_map);
    gather_kernel<<<NQ, 128>>>(out);
}

// round 4
// speedup vs baseline: 2.6460x; 1.2901x over previous
#include <cuda_runtime.h>
#include <cuda_bf16.h>
#include <math.h>
#include <stdint.h>

#define NQ 4096
#define NK 32768
#define DIN 1024
#define DQK 512
#define DV 512

// ---------------- scratch (no allocations allowed) ----------------
__device__ __nv_bfloat16 g_X1h[(size_t)NQ * DIN];
__device__ __nv_bfloat16 g_X1l[(size_t)NQ * DIN];
__device__ __nv_bfloat16 g_X2h[(size_t)NK * DIN];
__device__ __nv_bfloat16 g_X2l[(size_t)NK * DIN];
__device__ __nv_bfloat16 g_Wth[3 * 512 * DIN];   // transposed weights [n][k], hi
__device__ __nv_bfloat16 g_Wtl[3 * 512 * DIN];   // transposed weights [n][k], lo
__device__ float g_Q[(size_t)NQ * DQK];
__device__ float g_K[(size_t)NK * DQK];
__device__ float g_V[(size_t)NK * DV];
__device__ float g_S[NK];                 // per-key score
__device__ int   g_cnt[NQ];
__device__ int   g_off[NQ + 1];
__device__ int   g_cur[NQ];
__device__ int   g_idx[NK];

// ---------------- PTX helpers (portable sm_80+) ----------------
__device__ __forceinline__ void cp16(uint32_t dst, const void* src) {
    asm volatile("cp.async.cg.shared.global [%0], [%1], 16;" :: "r"(dst), "l"(src));
}
__device__ __forceinline__ void cp_commit() {
    asm volatile("cp.async.commit_group;" ::: "memory");
}
template <int N> __device__ __forceinline__ void cp_wait() {
    asm volatile("cp.async.wait_group %0;" :: "n"(N) : "memory");
}
__device__ __forceinline__ void ldsm4(uint32_t* r, uint32_t addr) {
    asm volatile("ldmatrix.sync.aligned.m8n8.x4.shared.b16 {%0,%1,%2,%3}, [%4];"
                 : "=r"(r[0]), "=r"(r[1]), "=r"(r[2]), "=r"(r[3]) : "r"(addr));
}
__device__ __forceinline__ void mma16816(float* c, const uint32_t* a, const uint32_t* b) {
    asm volatile(
        "mma.sync.aligned.m16n8k16.row.col.f32.bf16.bf16.f32 "
        "{%0,%1,%2,%3}, {%4,%5,%6,%7}, {%8,%9}, {%0,%1,%2,%3};"
        : "+f"(c[0]), "+f"(c[1]), "+f"(c[2]), "+f"(c[3])
        : "r"(a[0]), "r"(a[1]), "r"(a[2]), "r"(a[3]), "r"(b[0]), "r"(b[1]));
}

// ---------------- smem layout (compact 64B rows + chunk swizzle) ----------------
// Tile = 128 rows x 32 bf16 (64B). Chunk (16B) swizzle: c' = c ^ ((row>>1)&3).
// Conflict-free for ldmatrix 8-row phases and for cp.async fill.
#define TILE_B   8192
#define STAGE_B  (4 * TILE_B)          // Ah, Al, Bh, Bl = 32768
#define NSTAGE   3
#define GEMM_SMEM (NSTAGE * STAGE_B)   // 98304

// ---------------- fused 3-term bf16 HMMA GEMM ----------------
// C[M,512] = Ah*Bh + Ah*Bl + Al*Bh + bias.
// A: [M,1024] bf16 (hi/lo). B: [512,1024] bf16 ([n][k], hi/lo).
// grid = (512/128, M/128), block = 256 (8 warps, 2x4), warp tile 64x32.
__global__ __launch_bounds__(256, 2)
void gemm3_kernel(const __nv_bfloat16* __restrict__ Ah, const __nv_bfloat16* __restrict__ Al,
                  const __nv_bfloat16* __restrict__ Bh, const __nv_bfloat16* __restrict__ Bl,
                  const float* __restrict__ bias, float* __restrict__ C)
{
    extern __shared__ char smem[];
    const uint32_t sb = (uint32_t)__cvta_generic_to_shared(smem);
    const int tid = threadIdx.x, wid = tid >> 5, lane = tid & 31;
    const int warp_m = wid & 1, warp_n = wid >> 1;
    const int m_base = blockIdx.y * 128;
    const int n_base = blockIdx.x * 128;

    float acc[4][4][4];
    #pragma unroll
    for (int i = 0; i < 4; i++)
        #pragma unroll
        for (int j = 0; j < 4; j++)
            #pragma unroll
            for (int k = 0; k < 4; k++) acc[i][j][k] = 0.0f;

    // cp.async fill: tile has 512 chunks of 16B; thread handles chunks tid, tid+256
    const int fr0 = tid >> 2, fc0 = tid & 3;         // rows 0..63
    const int fr1 = fr0 + 64;                         // rows 64..127
    const uint32_t fd0 = (uint32_t)(fr0 * 64 + ((fc0 ^ ((fr0 >> 1) & 3)) << 4));
    const uint32_t fd1 = (uint32_t)(fr1 * 64 + ((fc0 ^ ((fr1 >> 1) & 3)) << 4));

    auto issue_loads = [&](int gi) {
        const int koff = gi * 32, s = gi % 3;
        const uint32_t st = sb + s * STAGE_B;
        const size_t aoff = (size_t)m_base * DIN + koff + fc0 * 8;
        const size_t boff = (size_t)n_base * DIN + koff + fc0 * 8;
        cp16(st + fd0,              Ah + aoff + (size_t)fr0 * DIN);
        cp16(st + fd1,              Ah + aoff + (size_t)fr1 * DIN);
        cp16(st + TILE_B + fd0,     Al + aoff + (size_t)fr0 * DIN);
        cp16(st + TILE_B + fd1,     Al + aoff + (size_t)fr1 * DIN);
        cp16(st + 2 * TILE_B + fd0, Bh + boff + (size_t)fr0 * DIN);
        cp16(st + 2 * TILE_B + fd1, Bh + boff + (size_t)fr1 * DIN);
        cp16(st + 3 * TILE_B + fd0, Bl + boff + (size_t)fr0 * DIN);
        cp16(st + 3 * TILE_B + fd1, Bl + boff + (size_t)fr1 * DIN);
        cp_commit();
    };

    issue_loads(0);
    issue_loads(1);

    // ldmatrix address components (per-thread constants)
    const int a_row = warp_m * 64 + (lane & 15);                    // + mf*16
    const int a_half = lane >> 4;                                    // 16B half within kh
    const int a_s = ((lane & 15) >> 1) & 3;                          // swizzle sel (mf*16 doesn't change it)
    const int b_row = warp_n * 32 + ((lane >> 4) << 3) + (lane & 7); // + nf2*16
    const int b_half = (lane >> 3) & 1;
    const int b_s = ((lane & 7) >> 1) & 3;

    const int NSTEP = 32;
    for (int gi = 0; gi < NSTEP; gi++) {
        if (gi + 2 < NSTEP) cp_wait<1>(); else cp_wait<0>();
        __syncthreads();
        if (gi + 2 < NSTEP) issue_loads(gi + 2);

        const uint32_t st = sb + (gi % 3) * STAGE_B;
        const uint32_t sAh = st, sAl = st + TILE_B;
        const uint32_t sBh = st + 2 * TILE_B, sBl = st + 3 * TILE_B;

        #pragma unroll
        for (int kh = 0; kh < 2; kh++) {
            const uint32_t acb = (uint32_t)(((kh * 2 + a_half) ^ a_s) << 4);
            const uint32_t bcb = (uint32_t)(((kh * 2 + b_half) ^ b_s) << 4);
            uint32_t bh[2][4], bl[2][4], af[4][4];
            #pragma unroll
            for (int nf2 = 0; nf2 < 2; nf2++) {
                const uint32_t ro = (uint32_t)((b_row + nf2 * 16) * 64) + bcb;
                ldsm4(bh[nf2], sBh + ro);
                ldsm4(bl[nf2], sBl + ro);
            }
            #pragma unroll
            for (int mf = 0; mf < 4; mf++)
                ldsm4(af[mf], sAh + (uint32_t)((a_row + mf * 16) * 64) + acb);
            #pragma unroll
            for (int mf = 0; mf < 4; mf++)
                #pragma unroll
                for (int nf = 0; nf < 4; nf++)
                    mma16816(acc[mf][nf], af[mf], &bh[nf >> 1][(nf & 1) * 2]);
            #pragma unroll
            for (int mf = 0; mf < 4; mf++)
                #pragma unroll
                for (int nf = 0; nf < 4; nf++)
                    mma16816(acc[mf][nf], af[mf], &bl[nf >> 1][(nf & 1) * 2]);
            #pragma unroll
            for (int mf = 0; mf < 4; mf++)
                ldsm4(af[mf], sAl + (uint32_t)((a_row + mf * 16) * 64) + acb);
            #pragma unroll
            for (int mf = 0; mf < 4; mf++)
                #pragma unroll
                for (int nf = 0; nf < 4; nf++)
                    mma16816(acc[mf][nf], af[mf], &bh[nf >> 1][(nf & 1) * 2]);
        }
    }

    // epilogue: add bias, store fp32
    const int col0 = n_base + warp_n * 32 + (lane & 3) * 2;
    const int r0   = m_base + warp_m * 64 + (lane >> 2);
    #pragma unroll
    for (int mf = 0; mf < 4; mf++) {
        #pragma unroll
        for (int nf = 0; nf < 4; nf++) {
            const int col = col0 + nf * 8;
            const float b0 = bias[col], b1 = bias[col + 1];
            float* p0 = C + (size_t)(r0 + mf * 16) * 512 + col;
            float* p1 = p0 + 8 * 512;
            *(float2*)p0 = make_float2(acc[mf][nf][0] + b0, acc[mf][nf][1] + b1);
            *(float2*)p1 = make_float2(acc[mf][nf][2] + b0, acc[mf][nf][3] + b1);
        }
    }
}

// ---------------- fp32 -> bf16 hi/lo split ----------------
__global__ void split_kernel(const float* __restrict__ x,
                             __nv_bfloat16* __restrict__ h, __nv_bfloat16* __restrict__ l)
{
    const size_t i = 4 * ((size_t)blockIdx.x * 256 + threadIdx.x);
    float4 v = *(const float4*)(x + i);
    __nv_bfloat16 h0 = __float2bfloat16(v.x), h1 = __float2bfloat16(v.y);
    __nv_bfloat16 h2 = __float2bfloat16(v.z), h3 = __float2bfloat16(v.w);
    __nv_bfloat16 l0 = __float2bfloat16(v.x - __bfloat162float(h0));
    __nv_bfloat16 l1 = __float2bfloat16(v.y - __bfloat162float(h1));
    __nv_bfloat16 l2 = __float2bfloat16(v.z - __bfloat162float(h2));
    __nv_bfloat16 l3 = __float2bfloat16(v.w - __bfloat162float(h3));
    __nv_bfloat162 hp0 = {h0, h1}, hp1 = {h2, h3}, lp0 = {l0, l1}, lp1 = {l2, l3};
    *(__nv_bfloat162*)(h + i)     = hp0;
    *(__nv_bfloat162*)(h + i + 2) = hp1;
    *(__nv_bfloat162*)(l + i)     = lp0;
    *(__nv_bfloat162*)(l + i + 2) = lp1;
}

// ---------------- W[k][n] (1024x512) -> Wt[n][k] hi/lo split ----------------
__global__ void wtrans_kernel(const float* __restrict__ W,
                              __nv_bfloat16* __restrict__ Th, __nv_bfloat16* __restrict__ Tl)
{
    __shared__ float tile[32][33];
    const int n0 = blockIdx.x * 32, k0 = blockIdx.y * 32;
    const int tx = threadIdx.x, ty = threadIdx.y;
    tile[ty][tx] = W[(size_t)(k0 + ty) * 512 + (n0 + tx)];
    __syncthreads();
    const float v = tile[tx][ty];                  // W[k0+tx][n0+ty]
    const __nv_bfloat16 h = __float2bfloat16(v);
    const __nv_bfloat16 l = __float2bfloat16(v - __bfloat162float(h));
    const size_t o = (size_t)(n0 + ty) * DIN + (k0 + tx);
    Th[o] = h;
    Tl[o] = l;
}

// ---------------- CSR build ----------------
__global__ void zero_cnt_kernel() {
    const int i = blockIdx.x * 256 + threadIdx.x;
    if (i < NQ) g_cnt[i] = 0;
}
__global__ void hist_kernel(const int* __restrict__ row_map) {
    const int j = blockIdx.x * 256 + threadIdx.x;
    if (j < NK) atomicAdd(&g_cnt[row_map[j]], 1);
}
__global__ void scan_kernel() {
    __shared__ int ssum[1024];
    const int t = threadIdx.x;
    const int4 c = *(const int4*)&g_cnt[4 * t];
    const int s = c.x + c.y + c.z + c.w;
    ssum[t] = s;
    __syncthreads();
    int run = s;
    for (int d = 1; d < 1024; d <<= 1) {
        int v = (t >= d) ? ssum[t - d] : 0;
        __syncthreads();
        ssum[t] += v;
        __syncthreads();
    }
    const int excl = ssum[t] - run;
    g_off[4 * t + 0] = excl;
    g_off[4 * t + 1] = excl + c.x;
    g_off[4 * t + 2] = excl + c.x + c.y;
    g_off[4 * t + 3] = excl + c.x + c.y + c.z;
    g_cur[4 * t + 0] = excl;
    g_cur[4 * t + 1] = excl + c.x;
    g_cur[4 * t + 2] = excl + c.x + c.y;
    g_cur[4 * t + 3] = excl + c.x + c.y + c.z;
    if (t == 1023) g_off[NQ] = ssum[t];
}
__global__ void fill_kernel(const int* __restrict__ row_map) {
    const int j = blockIdx.x * 256 + threadIdx.x;
    if (j < NK) {
        const int pos = atomicAdd(&g_cur[row_map[j]], 1);
        g_idx[pos] = j;
    }
}

// ---------------- scores: warp per key ----------------
__global__ void score_kernel(const int* __restrict__ row_map) {
    const int j    = blockIdx.x * 8 + (threadIdx.x >> 5);
    const int lane = threadIdx.x & 31;
    const int qi   = row_map[j];
    const float4* q4 = (const float4*)(g_Q + (size_t)qi * DQK);
    const float4* k4 = (const float4*)(g_K + (size_t)j * DQK);
    float s = 0.0f;
    #pragma unroll
    for (int t = 0; t < 4; t++) {
        float4 a = q4[lane + 32 * t];
        float4 b = k4[lane + 32 * t];
        s += a.x * b.x + a.y * b.y + a.z * b.z + a.w * b.w;
    }
    #pragma unroll
    for (int off = 16; off > 0; off >>= 1)
        s += __shfl_down_sync(0xFFFFFFFFu, s, off);
    if (lane == 0) g_S[j] = s * 0.044194173824159216f;   // 1/sqrt(512)
}

// ---------------- gather: per-query softmax + weighted V sum ----------------
__global__ void gather_kernel(float* __restrict__ out) {
    const int qi = blockIdx.x;
    const int s = g_off[qi], e = g_off[qi + 1];
    const int c = threadIdx.x;
    float* o = out + (size_t)qi * DV + c * 4;
    if (e == s) {
        *(float4*)o = make_float4(0.f, 0.f, 0.f, 0.f);
        return;
    }
    float m = -1e30f;
    for (int t = s; t < e; t++) m = fmaxf(m, g_S[g_idx[t]]);
    float4 acc = make_float4(0.f, 0.f, 0.f, 0.f);
    float den = 0.0f;
    for (int t = s; t < e; t++) {
        const int j = g_idx[t];
        const float w = expf(g_S[j] - m);
        den += w;
        const float4 v = *(const float4*)(g_V + (size_t)j * DV + c * 4);
        acc.x += w * v.x; acc.y += w * v.y; acc.z += w * v.z; acc.w += w * v.w;
    }
    const float inv = 1.0f / den;
    *(float4*)o = make_float4(acc.x * inv, acc.y * inv, acc.z * inv, acc.w * inv);
}

// ---------------- launcher ----------------
extern "C" void kernel_launch(void* const* d_in, const int* in_sizes, int n_in,
                              void* d_out, int out_size)
{
    const float* X1 = (const float*)d_in[0];
    const float* X2 = (const float*)d_in[1];
    const float* Wq = (const float*)d_in[2];
    const float* bq = (const float*)d_in[3];
    const float* Wk = (const float*)d_in[4];
    const float* bk = (const float*)d_in[5];
    const float* Wv = (const float*)d_in[6];
    const float* bv = (const float*)d_in[7];
    const int*   row_map = (const int*)d_in[8];
    float* out = (float*)d_out;

    __nv_bfloat16 *x1h, *x1l, *x2h, *x2l, *wth, *wtl;
    float *Qp, *Kp, *Vp;
    cudaGetSymbolAddress((void**)&x1h, g_X1h);
    cudaGetSymbolAddress((void**)&x1l, g_X1l);
    cudaGetSymbolAddress((void**)&x2h, g_X2h);
    cudaGetSymbolAddress((void**)&x2l, g_X2l);
    cudaGetSymbolAddress((void**)&wth, g_Wth);
    cudaGetSymbolAddress((void**)&wtl, g_Wtl);
    cudaGetSymbolAddress((void**)&Qp, g_Q);
    cudaGetSymbolAddress((void**)&Kp, g_K);
    cudaGetSymbolAddress((void**)&Vp, g_V);

    cudaFuncSetAttribute(gemm3_kernel, cudaFuncAttributeMaxDynamicSharedMemorySize, GEMM_SMEM);

    // splits + weight transpose
    split_kernel<<<(NQ * DIN) / 1024, 256>>>(X1, x1h, x1l);
    split_kernel<<<(NK * DIN) / 1024, 256>>>(X2, x2h, x2l);
    wtrans_kernel<<<dim3(512 / 32, DIN / 32), dim3(32, 32)>>>(Wq, wth + 0 * 512 * DIN, wtl + 0 * 512 * DIN);
    wtrans_kernel<<<dim3(512 / 32, DIN / 32), dim3(32, 32)>>>(Wk, wth + 1 * 512 * DIN, wtl + 1 * 512 * DIN);
    wtrans_kernel<<<dim3(512 / 32, DIN / 32), dim3(32, 32)>>>(Wv, wth + 2 * 512 * DIN, wtl + 2 * 512 * DIN);

    // fused HMMA projections
    gemm3_kernel<<<dim3(4, NQ / 128), 256, GEMM_SMEM>>>(x1h, x1l, wth + 0 * 512 * DIN, wtl + 0 * 512 * DIN, bq, Qp);
    gemm3_kernel<<<dim3(4, NK / 128), 256, GEMM_SMEM>>>(x2h, x2l, wth + 1 * 512 * DIN, wtl + 1 * 512 * DIN, bk, Kp);
    gemm3_kernel<<<dim3(4, NK / 128), 256, GEMM_SMEM>>>(x2h, x2l, wth + 2 * 512 * DIN, wtl + 2 * 512 * DIN, bv, Vp);

    // CSR over row_map
    zero_cnt_kernel<<<NQ / 256, 256>>>();
    hist_kernel<<<NK / 256, 256>>>(row_map);
    scan_kernel<<<1, 1024>>>();
    fill_kernel<<<NK / 256, 256>>>(row_map);

    // degenerate attention
    score_kernel<<<NK / 8, 256>>>(row_map);
    gather_kernel<<<NQ, 128>>>(out);
}

// round 5
// speedup vs baseline: 3.5100x; 1.3265x over previous
#include <cuda_runtime.h>
#include <cuda_fp16.h>
#include <math.h>
#include <stdint.h>

#define NQ 4096
#define NK 32768
#define DIN 1024
#define DQK 512
#define DV 512

// ---------------- scratch (no allocations allowed) ----------------
__device__ __half g_X1h[(size_t)NQ * DIN];
__device__ __half g_X1l[(size_t)NQ * DIN];
__device__ __half g_X2h[(size_t)NK * DIN];
__device__ __half g_X2l[(size_t)NK * DIN];
__device__ __half g_Wt[3 * 512 * DIN];    // transposed weights [n][k], fp16 (q|k|v)
__device__ float g_Q[(size_t)NQ * DQK];
__device__ float g_KV[(size_t)NK * 1024]; // row j: K[0..511] | V[512..1023]
__device__ float g_S[NK];                 // per-key score
__device__ int   g_cnt[NQ];
__device__ int   g_off[NQ + 1];
__device__ int   g_cur[NQ];
__device__ int   g_idx[NK];

// ---------------- PTX helpers (portable sm_80+) ----------------
__device__ __forceinline__ void cp16(uint32_t dst, const void* src) {
    asm volatile("cp.async.cg.shared.global [%0], [%1], 16;" :: "r"(dst), "l"(src));
}
__device__ __forceinline__ void cp_commit() {
    asm volatile("cp.async.commit_group;" ::: "memory");
}
template <int N> __device__ __forceinline__ void cp_wait() {
    asm volatile("cp.async.wait_group %0;" :: "n"(N) : "memory");
}
__device__ __forceinline__ void ldsm4(uint32_t* r, uint32_t addr) {
    asm volatile("ldmatrix.sync.aligned.m8n8.x4.shared.b16 {%0,%1,%2,%3}, [%4];"
                 : "=r"(r[0]), "=r"(r[1]), "=r"(r[2]), "=r"(r[3]) : "r"(addr));
}
__device__ __forceinline__ void mma16816(float* c, const uint32_t* a, const uint32_t* b) {
    asm volatile(
        "mma.sync.aligned.m16n8k16.row.col.f32.f16.f16.f32 "
        "{%0,%1,%2,%3}, {%4,%5,%6,%7}, {%8,%9}, {%0,%1,%2,%3};"
        : "+f"(c[0]), "+f"(c[1]), "+f"(c[2]), "+f"(c[3])
        : "r"(a[0]), "r"(a[1]), "r"(a[2]), "r"(a[3]), "r"(b[0]), "r"(b[1]));
}

// ---------------- smem layout (compact 64B rows + chunk swizzle) ----------------
// Tile = 128 rows x 32 fp16 (64B). Chunk (16B) swizzle: c' = c ^ ((row>>1)&3).
#define TILE_B   8192
#define STAGE_B  (3 * TILE_B)          // Ah, Al, B = 24576
#define NSTAGE   4
#define GEMM_SMEM (NSTAGE * STAGE_B)   // 98304

// ---------------- fused 2-term fp16 HMMA GEMM ----------------
// C[M, N] = (Ah + Al) * B^T + bias.  A: [M,1024] fp16 hi/lo. B: [N,1024] fp16.
// grid = (N/128, M/128), block = 256 (8 warps, 2x4), warp tile 64x32.
__global__ __launch_bounds__(256, 2)
void gemm2_kernel(const __half* __restrict__ Ah, const __half* __restrict__ Al,
                  const __half* __restrict__ B,
                  const float* __restrict__ bias0, const float* __restrict__ bias1,
                  float* __restrict__ C, int ldc)
{
    extern __shared__ char smem[];
    const uint32_t sb = (uint32_t)__cvta_generic_to_shared(smem);
    const int tid = threadIdx.x, wid = tid >> 5, lane = tid & 31;
    const int warp_m = wid & 1, warp_n = wid >> 1;
    const int m_base = blockIdx.y * 128;
    const int n_base = blockIdx.x * 128;

    float acc[4][4][4];
    #pragma unroll
    for (int i = 0; i < 4; i++)
        #pragma unroll
        for (int j = 0; j < 4; j++)
            #pragma unroll
            for (int k = 0; k < 4; k++) acc[i][j][k] = 0.0f;

    // cp.async fill: tile has 512 chunks of 16B; thread handles chunks tid, tid+256
    const int fr0 = tid >> 2, fc0 = tid & 3;         // rows 0..63
    const int fr1 = fr0 + 64;                         // rows 64..127
    const uint32_t fd0 = (uint32_t)(fr0 * 64 + ((fc0 ^ ((fr0 >> 1) & 3)) << 4));
    const uint32_t fd1 = (uint32_t)(fr1 * 64 + ((fc0 ^ ((fr1 >> 1) & 3)) << 4));

    auto issue_loads = [&](int gi) {
        const int koff = gi * 32, s = gi & 3;
        const uint32_t st = sb + s * STAGE_B;
        const size_t aoff = (size_t)m_base * DIN + koff + fc0 * 8;
        const size_t boff = (size_t)n_base * DIN + koff + fc0 * 8;
        cp16(st + fd0,              Ah + aoff + (size_t)fr0 * DIN);
        cp16(st + fd1,              Ah + aoff + (size_t)fr1 * DIN);
        cp16(st + TILE_B + fd0,     Al + aoff + (size_t)fr0 * DIN);
        cp16(st + TILE_B + fd1,     Al + aoff + (size_t)fr1 * DIN);
        cp16(st + 2 * TILE_B + fd0, B + boff + (size_t)fr0 * DIN);
        cp16(st + 2 * TILE_B + fd1, B + boff + (size_t)fr1 * DIN);
        cp_commit();
    };

    issue_loads(0);
    issue_loads(1);
    issue_loads(2);

    // ldmatrix address components (per-thread constants)
    const int a_row = warp_m * 64 + (lane & 15);                    // + mf*16
    const int a_half = lane >> 4;
    const int a_s = ((lane & 15) >> 1) & 3;
    const int b_row = warp_n * 32 + ((lane >> 4) << 3) + (lane & 7); // + nf2*16
    const int b_half = (lane >> 3) & 1;
    const int b_s = ((lane & 7) >> 1) & 3;

    const int NSTEP = 32;
    for (int gi = 0; gi < NSTEP; gi++) {
        if (gi + 3 < NSTEP) cp_wait<2>(); else cp_wait<0>();
        __syncthreads();
        if (gi + 3 < NSTEP) issue_loads(gi + 3);

        const uint32_t st = sb + (gi & 3) * STAGE_B;
        const uint32_t sAh = st, sAl = st + TILE_B, sB = st + 2 * TILE_B;

        #pragma unroll
        for (int kh = 0; kh < 2; kh++) {
            const uint32_t acb = (uint32_t)(((kh * 2 + a_half) ^ a_s) << 4);
            const uint32_t bcb = (uint32_t)(((kh * 2 + b_half) ^ b_s) << 4);
            uint32_t bf[2][4], af[4][4];
            #pragma unroll
            for (int nf2 = 0; nf2 < 2; nf2++)
                ldsm4(bf[nf2], sB + (uint32_t)((b_row + nf2 * 16) * 64) + bcb);
            #pragma unroll
            for (int mf = 0; mf < 4; mf++)
                ldsm4(af[mf], sAh + (uint32_t)((a_row + mf * 16) * 64) + acb);
            #pragma unroll
            for (int mf = 0; mf < 4; mf++)
                #pragma unroll
                for (int nf = 0; nf < 4; nf++)
                    mma16816(acc[mf][nf], af[mf], &bf[nf >> 1][(nf & 1) * 2]);
            #pragma unroll
            for (int mf = 0; mf < 4; mf++)
                ldsm4(af[mf], sAl + (uint32_t)((a_row + mf * 16) * 64) + acb);
            #pragma unroll
            for (int mf = 0; mf < 4; mf++)
                #pragma unroll
                for (int nf = 0; nf < 4; nf++)
                    mma16816(acc[mf][nf], af[mf], &bf[nf >> 1][(nf & 1) * 2]);
        }
    }

    // epilogue: add bias, store fp32 (whole CTA n-block is in one bias half)
    const float* bias = (n_base < 512) ? bias0 : (bias1 - 512);
    const int col0 = n_base + warp_n * 32 + (lane & 3) * 2;
    const int r0   = m_base + warp_m * 64 + (lane >> 2);
    #pragma unroll
    for (int mf = 0; mf < 4; mf++) {
        #pragma unroll
        for (int nf = 0; nf < 4; nf++) {
            const int col = col0 + nf * 8;
            const float b0 = bias[col], b1 = bias[col + 1];
            float* p0 = C + (size_t)(r0 + mf * 16) * ldc + col;
            float* p1 = p0 + 8 * ldc;
            *(float2*)p0 = make_float2(acc[mf][nf][0] + b0, acc[mf][nf][1] + b1);
            *(float2*)p1 = make_float2(acc[mf][nf][2] + b0, acc[mf][nf][3] + b1);
        }
    }
}

// ---------------- fp32 -> fp16 hi/lo split ----------------
__global__ void split_kernel(const float* __restrict__ x,
                             __half* __restrict__ h, __half* __restrict__ l)
{
    const size_t i = 4 * ((size_t)blockIdx.x * 256 + threadIdx.x);
    float4 v = *(const float4*)(x + i);
    __half h0 = __float2half(v.x), h1 = __float2half(v.y);
    __half h2 = __float2half(v.z), h3 = __float2half(v.w);
    __half l0 = __float2half(v.x - __half2float(h0));
    __half l1 = __float2half(v.y - __half2float(h1));
    __half l2 = __float2half(v.z - __half2float(h2));
    __half l3 = __float2half(v.w - __half2float(h3));
    __half2 hp0 = {h0, h1}, hp1 = {h2, h3}, lp0 = {l0, l1}, lp1 = {l2, l3};
    *(__half2*)(h + i)     = hp0;
    *(__half2*)(h + i + 2) = hp1;
    *(__half2*)(l + i)     = lp0;
    *(__half2*)(l + i + 2) = lp1;
}

// ---------------- W[k][n] (1024x512) -> Wt[n][k] fp16, all 3 weights ----------------
__global__ void wtrans_kernel(const float* __restrict__ Wq, const float* __restrict__ Wk,
                              const float* __restrict__ Wv, __half* __restrict__ T)
{
    __shared__ float tile[32][33];
    const float* W = (blockIdx.z == 0) ? Wq : (blockIdx.z == 1) ? Wk : Wv;
    __half* Th = T + (size_t)blockIdx.z * 512 * DIN;
    const int n0 = blockIdx.x * 32, k0 = blockIdx.y * 32;
    const int tx = threadIdx.x, ty = threadIdx.y;
    tile[ty][tx] = W[(size_t)(k0 + ty) * 512 + (n0 + tx)];
    __syncthreads();
    Th[(size_t)(n0 + ty) * DIN + (k0 + tx)] = __float2half(tile[tx][ty]);
}

// ---------------- CSR build ----------------
__global__ void zero_cnt_kernel() {
    const int i = blockIdx.x * 256 + threadIdx.x;
    if (i < NQ) g_cnt[i] = 0;
}
__global__ void hist_kernel(const int* __restrict__ row_map) {
    const int j = blockIdx.x * 256 + threadIdx.x;
    if (j < NK) atomicAdd(&g_cnt[row_map[j]], 1);
}
__global__ void scan_kernel() {
    __shared__ int ssum[1024];
    const int t = threadIdx.x;
    const int4 c = *(const int4*)&g_cnt[4 * t];
    const int s = c.x + c.y + c.z + c.w;
    ssum[t] = s;
    __syncthreads();
    int run = s;
    for (int d = 1; d < 1024; d <<= 1) {
        int v = (t >= d) ? ssum[t - d] : 0;
        __syncthreads();
        ssum[t] += v;
        __syncthreads();
    }
    const int excl = ssum[t] - run;
    g_off[4 * t + 0] = excl;
    g_off[4 * t + 1] = excl + c.x;
    g_off[4 * t + 2] = excl + c.x + c.y;
    g_off[4 * t + 3] = excl + c.x + c.y + c.z;
    g_cur[4 * t + 0] = excl;
    g_cur[4 * t + 1] = excl + c.x;
    g_cur[4 * t + 2] = excl + c.x + c.y;
    g_cur[4 * t + 3] = excl + c.x + c.y + c.z;
    if (t == 1023) g_off[NQ] = ssum[t];
}
__global__ void fill_kernel(const int* __restrict__ row_map) {
    const int j = blockIdx.x * 256 + threadIdx.x;
    if (j < NK) {
        const int pos = atomicAdd(&g_cur[row_map[j]], 1);
        g_idx[pos] = j;
    }
}

// ---------------- scores: warp per key, K = g_KV[j][0..511] ----------------
__global__ void score_kernel(const int* __restrict__ row_map) {
    const int j    = blockIdx.x * 8 + (threadIdx.x >> 5);
    const int lane = threadIdx.x & 31;
    const int qi   = row_map[j];
    const float4* q4 = (const float4*)(g_Q + (size_t)qi * DQK);
    const float4* k4 = (const float4*)(g_KV + (size_t)j * 1024);
    float s = 0.0f;
    #pragma unroll
    for (int t = 0; t < 4; t++) {
        float4 a = q4[lane + 32 * t];
        float4 b = k4[lane + 32 * t];
        s += a.x * b.x + a.y * b.y + a.z * b.z + a.w * b.w;
    }
    #pragma unroll
    for (int off = 16; off > 0; off >>= 1)
        s += __shfl_down_sync(0xFFFFFFFFu, s, off);
    if (lane == 0) g_S[j] = s * 0.044194173824159216f;   // 1/sqrt(512)
}

// ---------------- gather: per-query softmax + weighted V sum ----------------
__global__ void gather_kernel(float* __restrict__ out) {
    const int qi = blockIdx.x;
    const int s = g_off[qi], e = g_off[qi + 1];
    const int c = threadIdx.x;
    float* o = out + (size_t)qi * DV + c * 4;
    if (e == s) {
        *(float4*)o = make_float4(0.f, 0.f, 0.f, 0.f);
        return;
    }
    float m = -1e30f;
    for (int t = s; t < e; t++) m = fmaxf(m, g_S[g_idx[t]]);
    float4 acc = make_float4(0.f, 0.f, 0.f, 0.f);
    float den = 0.0f;
    for (int t = s; t < e; t++) {
        const int j = g_idx[t];
        const float w = expf(g_S[j] - m);
        den += w;
        const float4 v = *(const float4*)(g_KV + (size_t)j * 1024 + 512 + c * 4);
        acc.x += w * v.x; acc.y += w * v.y; acc.z += w * v.z; acc.w += w * v.w;
    }
    const float inv = 1.0f / den;
    *(float4*)o = make_float4(acc.x * inv, acc.y * inv, acc.z * inv, acc.w * inv);
}

// ---------------- launcher ----------------
extern "C" void kernel_launch(void* const* d_in, const int* in_sizes, int n_in,
                              void* d_out, int out_size)
{
    const float* X1 = (const float*)d_in[0];
    const float* X2 = (const float*)d_in[1];
    const float* Wq = (const float*)d_in[2];
    const float* bq = (const float*)d_in[3];
    const float* Wk = (const float*)d_in[4];
    const float* bk = (const float*)d_in[5];
    const float* Wv = (const float*)d_in[6];
    const float* bv = (const float*)d_in[7];
    const int*   row_map = (const int*)d_in[8];
    float* out = (float*)d_out;

    __half *x1h, *x1l, *x2h, *x2l, *wt;
    float *Qp, *KVp;
    cudaGetSymbolAddress((void**)&x1h, g_X1h);
    cudaGetSymbolAddress((void**)&x1l, g_X1l);
    cudaGetSymbolAddress((void**)&x2h, g_X2h);
    cudaGetSymbolAddress((void**)&x2l, g_X2l);
    cudaGetSymbolAddress((void**)&wt, g_Wt);
    cudaGetSymbolAddress((void**)&Qp, g_Q);
    cudaGetSymbolAddress((void**)&KVp, g_KV);

    cudaFuncSetAttribute(gemm2_kernel, cudaFuncAttributeMaxDynamicSharedMemorySize, GEMM_SMEM);

    // prep (ordered so ncu -s 5 captures the big KV GEMM as launch #6)
    split_kernel<<<(NQ * DIN) / 1024, 256>>>(X1, x1h, x1l);
    split_kernel<<<(NK * DIN) / 1024, 256>>>(X2, x2h, x2l);
    wtrans_kernel<<<dim3(16, 32, 3), dim3(32, 32)>>>(Wq, Wk, Wv, wt);
    zero_cnt_kernel<<<NQ / 256, 256>>>();

    // fp16 2-term projections
    gemm2_kernel<<<dim3(4, NQ / 128), 256, GEMM_SMEM>>>(x1h, x1l, wt, bq, bq, Qp, 512);
    gemm2_kernel<<<dim3(8, NK / 128), 256, GEMM_SMEM>>>(x2h, x2l, wt + (size_t)512 * DIN,
                                                        bk, bv, KVp, 1024);

    // CSR over row_map
    hist_kernel<<<NK / 256, 256>>>(row_map);
    scan_kernel<<<1, 1024>>>();
    fill_kernel<<<NK / 256, 256>>>(row_map);

    // degenerate attention
    score_kernel<<<NK / 8, 256>>>(row_map);
    gather_kernel<<<NQ, 128>>>(out);
}